// round 3
// baseline (speedup 1.0000x reference)
#include <cuda_runtime.h>
#include <math.h>

#define NN   50000
#define FIN  128
#define C1   128          // HEADS*HID
#define HEADS 4
#define HID  32
#define CLS  40
#define EE   800000
#define TOTE (EE + NN)    // edges + self loops = 850000
#define NEG  0.2f

// ---------------- scratch (no allocations allowed) ----------------
__device__ float g_h1  [NN * C1];      // layer-1 linear output
__device__ float g_out1[NN * C1];      // layer-1 aggregated output (atomic acc)
__device__ float g_als1[NN * HEADS];
__device__ float g_ald1[NN * HEADS];
__device__ float g_den1[NN * HEADS];
__device__ float g_w1  [TOTE * HEADS];
__device__ float g_h2  [NN * CLS];
__device__ float g_als2[NN];
__device__ float g_ald2[NN];
__device__ float g_den2[NN];
__device__ float g_w2  [TOTE];

__device__ __forceinline__ float lrelu(float x) { return x > 0.f ? x : NEG * x; }

__device__ __forceinline__ void red4(float* p, float a, float b, float c, float d) {
    asm volatile("red.global.add.v4.f32 [%0], {%1,%2,%3,%4};"
                 :: "l"(p), "f"(a), "f"(b), "f"(c), "f"(d) : "memory");
}

// ---------------- zero accumulators ----------------
__global__ void zero_kernel(float* __restrict__ out) {
    int i = blockIdx.x * blockDim.x + threadIdx.x;
    int stride = gridDim.x * blockDim.x;
    for (int j = i; j < NN * C1 / 4; j += stride)
        ((float4*)g_out1)[j] = make_float4(0.f, 0.f, 0.f, 0.f);
    for (int j = i; j < NN * CLS / 4; j += stride)
        ((float4*)out)[j] = make_float4(0.f, 0.f, 0.f, 0.f);
    for (int j = i; j < NN * HEADS; j += stride) g_den1[j] = 0.f;
    for (int j = i; j < NN; j += stride)         g_den2[j] = 0.f;
}

// ---------------- GEMM1: h1 = x @ W1  (N x 128 @ 128 x 128) ----------------
// block: 256 threads -> 64 rows x 128 cols tile; k-tiles of 64; 48KB smem
__global__ void gemm1_kernel(const float* __restrict__ x, const float* __restrict__ W) {
    __shared__ __align__(16) float xs[64][64];
    __shared__ __align__(16) float ws[64][128];
    int t = threadIdx.x;
    int row0 = blockIdx.x * 64;
    int tc = t & 31;        // col group: cols tc*4 .. tc*4+3
    int tr = t >> 5;        // row group: rows tr*8 .. tr*8+7

    float4 acc[8];
#pragma unroll
    for (int r = 0; r < 8; r++) acc[r] = make_float4(0.f, 0.f, 0.f, 0.f);

    for (int k0 = 0; k0 < FIN; k0 += 64) {
        // load x tile [64 rows][64 k]
#pragma unroll
        for (int j = 0; j < 4; j++) {
            int flat = (t + 256 * j) * 4;
            int r = flat >> 6, k = flat & 63;
            int gr = row0 + r;
            float4 v = make_float4(0.f, 0.f, 0.f, 0.f);
            if (gr < NN) v = *(const float4*)&x[gr * FIN + k0 + k];
            *(float4*)&xs[r][k] = v;
        }
        // load W tile [64 k][128 cols]
#pragma unroll
        for (int j = 0; j < 8; j++) {
            int flat = (t + 256 * j) * 4;
            int r = flat >> 7, c = flat & 127;
            *(float4*)&ws[r][c] = *(const float4*)&W[(k0 + r) * C1 + c];
        }
        __syncthreads();
#pragma unroll 8
        for (int kk = 0; kk < 64; kk++) {
            float4 w4 = *(float4*)&ws[kk][tc * 4];
#pragma unroll
            for (int r = 0; r < 8; r++) {
                float xv = xs[tr * 8 + r][kk];
                acc[r].x += xv * w4.x;
                acc[r].y += xv * w4.y;
                acc[r].z += xv * w4.z;
                acc[r].w += xv * w4.w;
            }
        }
        __syncthreads();
    }
#pragma unroll
    for (int r = 0; r < 8; r++) {
        int gr = row0 + tr * 8 + r;
        if (gr < NN) *(float4*)&g_h1[gr * C1 + tc * 4] = acc[r];
    }
}

// ---------------- attention logits layer 1 (warp per node) ----------------
__global__ void att1_kernel(const float* __restrict__ att_s, const float* __restrict__ att_d) {
    int gt = blockIdx.x * blockDim.x + threadIdx.x;
    int n = gt >> 5, lane = gt & 31;
    if (n >= NN) return;
    float4 h  = *(const float4*)&g_h1[n * C1 + lane * 4];
    float4 as = *(const float4*)&att_s[lane * 4];
    float4 ad = *(const float4*)&att_d[lane * 4];
    float ps = h.x * as.x + h.y * as.y + h.z * as.z + h.w * as.w;
    float pd = h.x * ad.x + h.y * ad.y + h.z * ad.z + h.w * ad.w;
    // reduce groups of 8 lanes (one head per group)
    ps += __shfl_down_sync(0xffffffff, ps, 4);
    ps += __shfl_down_sync(0xffffffff, ps, 2);
    ps += __shfl_down_sync(0xffffffff, ps, 1);
    pd += __shfl_down_sync(0xffffffff, pd, 4);
    pd += __shfl_down_sync(0xffffffff, pd, 2);
    pd += __shfl_down_sync(0xffffffff, pd, 1);
    if ((lane & 7) == 0) {
        int h_idx = lane >> 3;
        g_als1[n * HEADS + h_idx] = ps;
        g_ald1[n * HEADS + h_idx] = pd;
    }
}

// ---------------- edge pass 1a: weights + denominators (layer 1) ----------------
__global__ void edge1a_kernel(const int* __restrict__ ei) {
    int e = blockIdx.x * blockDim.x + threadIdx.x;
    if (e >= TOTE) return;
    int s, d;
    if (e < EE) { s = ei[e]; d = ei[EE + e]; } else { s = d = e - EE; }
    float4 as = *(const float4*)&g_als1[s * HEADS];
    float4 ad = *(const float4*)&g_ald1[d * HEADS];
    float4 w;
    w.x = __expf(lrelu(as.x + ad.x));
    w.y = __expf(lrelu(as.y + ad.y));
    w.z = __expf(lrelu(as.z + ad.z));
    w.w = __expf(lrelu(as.w + ad.w));
    *(float4*)&g_w1[e * HEADS] = w;
    red4(&g_den1[d * HEADS], w.x, w.y, w.z, w.w);
}

// ---------------- edge pass 1b: weighted scatter (warp per edge) ----------------
__global__ void edge1b_kernel(const int* __restrict__ ei) {
    int gt = blockIdx.x * blockDim.x + threadIdx.x;
    int e = gt >> 5, lane = gt & 31;
    if (e >= TOTE) return;
    int s, d;
    if (e < EE) { s = ei[e]; d = ei[EE + e]; } else { s = d = e - EE; }
    float4 w4 = *(const float4*)&g_w1[e * HEADS];
    float4 dn = *(const float4*)&g_den1[d * HEADS];
    int h = lane >> 3;
    float wv = (h == 0) ? w4.x : (h == 1) ? w4.y : (h == 2) ? w4.z : w4.w;
    float dv = (h == 0) ? dn.x : (h == 1) ? dn.y : (h == 2) ? dn.z : dn.w;
    float alpha = wv / (dv + 1e-16f);
    float4 hv = *(const float4*)&g_h1[s * C1 + lane * 4];
    red4(&g_out1[d * C1 + lane * 4],
         hv.x * alpha, hv.y * alpha, hv.z * alpha, hv.w * alpha);
}

// ---------------- ReLU + bias + GEMM2 + layer-2 logits (thread per node) ----------------
__global__ void l2gemm_kernel(const float* __restrict__ W2, const float* __restrict__ b1,
                              const float* __restrict__ as2, const float* __restrict__ ad2) {
    __shared__ float W2s[FIN * CLS];
    __shared__ float b1s[FIN];
    __shared__ float s2s[CLS], d2s[CLS];
    int t = threadIdx.x;
    for (int i = t; i < FIN * CLS; i += blockDim.x) W2s[i] = W2[i];
    if (t < FIN) b1s[t] = b1[t];
    if (t < CLS) { s2s[t] = as2[t]; d2s[t] = ad2[t]; }
    __syncthreads();

    int n = blockIdx.x * blockDim.x + t;
    if (n >= NN) return;
    float acc[CLS];
#pragma unroll
    for (int c = 0; c < CLS; c++) acc[c] = 0.f;
    for (int k = 0; k < FIN; k++) {
        float rv = g_out1[n * FIN + k] + b1s[k];
        rv = fmaxf(rv, 0.f);
#pragma unroll
        for (int c = 0; c < CLS; c++) acc[c] += rv * W2s[k * CLS + c];
    }
    float ls = 0.f, ld = 0.f;
#pragma unroll
    for (int c = 0; c < CLS; c++) {
        g_h2[n * CLS + c] = acc[c];
        ls += acc[c] * s2s[c];
        ld += acc[c] * d2s[c];
    }
    g_als2[n] = ls;
    g_ald2[n] = ld;
}

// ---------------- edge pass 2a: scalar weights + denom ----------------
__global__ void edge2a_kernel(const int* __restrict__ ei) {
    int e = blockIdx.x * blockDim.x + threadIdx.x;
    if (e >= TOTE) return;
    int s, d;
    if (e < EE) { s = ei[e]; d = ei[EE + e]; } else { s = d = e - EE; }
    float w = __expf(lrelu(g_als2[s] + g_ald2[d]));
    g_w2[e] = w;
    atomicAdd(&g_den2[d], w);
}

// ---------------- edge pass 2b: weighted scatter into d_out (chunked) ----------------
__global__ void edge2b_kernel(const int* __restrict__ ei, float* __restrict__ out) {
    long long idx = (long long)blockIdx.x * blockDim.x + threadIdx.x;
    if (idx >= (long long)TOTE * 10) return;
    int e = (int)(idx / 10);
    int q = (int)(idx - (long long)e * 10);
    int s, d;
    if (e < EE) { s = ei[e]; d = ei[EE + e]; } else { s = d = e - EE; }
    float alpha = g_w2[e] / (g_den2[d] + 1e-16f);
    float4 hv = *(const float4*)&g_h2[s * CLS + q * 4];
    red4(&out[d * CLS + q * 4],
         hv.x * alpha, hv.y * alpha, hv.z * alpha, hv.w * alpha);
}

// ---------------- finalize: +b2, log_softmax (warp per node) ----------------
__global__ void final_kernel(float* __restrict__ out, const float* __restrict__ b2) {
    int gt = blockIdx.x * blockDim.x + threadIdx.x;
    int n = gt >> 5, lane = gt & 31;
    if (n >= NN) return;
    float a = out[n * CLS + lane] + b2[lane];
    float b = -1e30f;
    if (lane < 8) b = out[n * CLS + 32 + lane] + b2[32 + lane];
    float m = fmaxf(a, b);
#pragma unroll
    for (int o = 16; o > 0; o >>= 1) m = fmaxf(m, __shfl_xor_sync(0xffffffff, m, o));
    float sum = __expf(a - m) + (lane < 8 ? __expf(b - m) : 0.f);
#pragma unroll
    for (int o = 16; o > 0; o >>= 1) sum += __shfl_xor_sync(0xffffffff, sum, o);
    float lse = logf(sum);
    out[n * CLS + lane] = a - m - lse;
    if (lane < 8) out[n * CLS + 32 + lane] = b - m - lse;
}

// ---------------- launch ----------------
extern "C" void kernel_launch(void* const* d_in, const int* in_sizes, int n_in,
                              void* d_out, int out_size) {
    const float* x   = (const float*)d_in[0];
    const int*   ei  = (const int*)  d_in[1];
    const float* W1  = (const float*)d_in[2];
    const float* as1 = (const float*)d_in[3];
    const float* ad1 = (const float*)d_in[4];
    const float* b1  = (const float*)d_in[5];
    const float* W2  = (const float*)d_in[6];
    const float* as2 = (const float*)d_in[7];
    const float* ad2 = (const float*)d_in[8];
    const float* b2  = (const float*)d_in[9];
    float* out = (float*)d_out;

    zero_kernel<<<4096, 256>>>(out);
    gemm1_kernel<<<(NN + 63) / 64, 256>>>(x, W1);
    att1_kernel<<<(NN * 32 + 255) / 256, 256>>>(as1, ad1);
    edge1a_kernel<<<(TOTE + 255) / 256, 256>>>(ei);
    edge1b_kernel<<<(TOTE * 32 + 255) / 256, 256>>>(ei);
    l2gemm_kernel<<<(NN + 255) / 256, 256>>>(W2, b1, as2, ad2);
    edge2a_kernel<<<(TOTE + 255) / 256, 256>>>(ei);
    edge2b_kernel<<<(int)(((long long)TOTE * 10 + 255) / 256), 256>>>(ei, out);
    final_kernel<<<(NN * 32 + 255) / 256, 256>>>(out, b2);
}

// round 4
// speedup vs baseline: 1.1176x; 1.1176x over previous
#include <cuda_runtime.h>
#include <math.h>

#define NN    50000
#define FIN   128
#define C1    128
#define HEADS 4
#define HID   32
#define CLS   40
#define EE    800000
#define TOTE  (EE + NN)
#define NEG   0.2f

// ---------------- scratch ----------------
__device__ float g_h1  [NN * C1];
__device__ float g_out1[NN * C1];      // relu(agg + b1)
__device__ float g_als1[NN * HEADS];
__device__ float g_ald1[NN * HEADS];
__device__ float g_h2  [NN * CLS];
__device__ float g_als2[NN];
__device__ float g_ald2[NN];
__device__ int   g_cnt [NN];           // histogram, then cursor
__device__ int   g_rowptr[NN + 1];
__device__ int   g_csr_src[TOTE];

__device__ __forceinline__ float lrelu(float x) { return x > 0.f ? x : NEG * x; }

// ---- packed f32x2 helpers (sm_103a dual-rate fp32) ----
__device__ __forceinline__ unsigned long long pk2(float a, float b) {
    unsigned long long r;
    asm("mov.b64 %0, {%1, %2};" : "=l"(r)
        : "r"(__float_as_uint(a)), "r"(__float_as_uint(b)));
    return r;
}
__device__ __forceinline__ void fma2(unsigned long long& d,
                                     unsigned long long a, unsigned long long b) {
    asm("fma.rn.f32x2 %0, %1, %2, %0;" : "+l"(d) : "l"(a), "l"(b));
}

// ---------------- CSR build ----------------
__global__ void zero_cnt_kernel() {
    int i = blockIdx.x * blockDim.x + threadIdx.x;
    if (i < NN) g_cnt[i] = 0;
}
__global__ void hist_kernel(const int* __restrict__ ei) {
    int e = blockIdx.x * blockDim.x + threadIdx.x;
    if (e >= TOTE) return;
    int d = (e < EE) ? ei[EE + e] : e - EE;
    atomicAdd(&g_cnt[d], 1);
}
__global__ void scan_kernel() {
    __shared__ int sums[1024];
    const int CH = 49;                    // 1024*49 = 50176 >= NN
    int tid = threadIdx.x;
    int base = tid * CH;
    int s = 0;
#pragma unroll 7
    for (int j = 0; j < CH; j++) { int idx = base + j; if (idx < NN) s += g_cnt[idx]; }
    sums[tid] = s;
    __syncthreads();
    for (int off = 1; off < 1024; off <<= 1) {
        int v = (tid >= off) ? sums[tid - off] : 0;
        __syncthreads();
        sums[tid] += v;
        __syncthreads();
    }
    int run = sums[tid] - s;              // exclusive
    for (int j = 0; j < CH; j++) {
        int idx = base + j;
        if (idx < NN) {
            int c = g_cnt[idx];
            g_rowptr[idx] = run;
            g_cnt[idx] = run;             // cursor for scatter
            run += c;
        }
    }
    if (tid == 1023) g_rowptr[NN] = sums[tid];
}
__global__ void scatter_kernel(const int* __restrict__ ei) {
    int e = blockIdx.x * blockDim.x + threadIdx.x;
    if (e >= TOTE) return;
    int s, d;
    if (e < EE) { s = ei[e]; d = ei[EE + e]; } else { s = d = e - EE; }
    int pos = atomicAdd(&g_cnt[d], 1);
    g_csr_src[pos] = s;
}

// ---------------- GEMM1: h1 = x @ W1  (128x128 tile, 8x8/thread, f32x2) ----------------
__global__ __launch_bounds__(256, 2) void gemm1_kernel(const float* __restrict__ x,
                                                       const float* __restrict__ W) {
    __shared__ __align__(16) float xst[32][132];   // [kk][row], transposed
    __shared__ __align__(16) float ws [32][128];   // [kk][col]
    int t = threadIdx.x;
    int row0 = blockIdx.x * 128;
    int tr = t & 15, tc = t >> 4;                  // 16x16 thread grid

    unsigned long long acc[8][4];
#pragma unroll
    for (int r = 0; r < 8; r++)
#pragma unroll
        for (int c = 0; c < 4; c++) acc[r][c] = 0ULL;

    for (int k0 = 0; k0 < FIN; k0 += 32) {
#pragma unroll
        for (int j = 0; j < 4; j++) {
            int idx = t + 256 * j;                 // [0,1024)
            int r = idx >> 3, kq = idx & 7;
            int gr = row0 + r;
            float4 v = make_float4(0.f, 0.f, 0.f, 0.f);
            if (gr < NN) v = *(const float4*)&x[gr * FIN + k0 + kq * 4];
            xst[kq * 4 + 0][r] = v.x;
            xst[kq * 4 + 1][r] = v.y;
            xst[kq * 4 + 2][r] = v.z;
            xst[kq * 4 + 3][r] = v.w;
        }
#pragma unroll
        for (int j = 0; j < 4; j++) {
            int idx = t + 256 * j;
            int kk = idx >> 5, c4 = idx & 31;
            *(float4*)&ws[kk][c4 * 4] = *(const float4*)&W[(k0 + kk) * C1 + c4 * 4];
        }
        __syncthreads();
#pragma unroll 4
        for (int kk = 0; kk < 32; kk++) {
            float4 a0 = *(float4*)&xst[kk][tr * 8];
            float4 a1 = *(float4*)&xst[kk][tr * 8 + 4];
            ulonglong2 b0 = *(ulonglong2*)&ws[kk][tc * 8];
            ulonglong2 b1 = *(ulonglong2*)&ws[kk][tc * 8 + 4];
            float av[8] = {a0.x, a0.y, a0.z, a0.w, a1.x, a1.y, a1.z, a1.w};
#pragma unroll
            for (int r = 0; r < 8; r++) {
                unsigned long long ap = pk2(av[r], av[r]);
                fma2(acc[r][0], ap, b0.x);
                fma2(acc[r][1], ap, b0.y);
                fma2(acc[r][2], ap, b1.x);
                fma2(acc[r][3], ap, b1.y);
            }
        }
        __syncthreads();
    }
#pragma unroll
    for (int r = 0; r < 8; r++) {
        int gr = row0 + tr * 8 + r;
        if (gr < NN) {
            ulonglong2 s0; s0.x = acc[r][0]; s0.y = acc[r][1];
            ulonglong2 s1; s1.x = acc[r][2]; s1.y = acc[r][3];
            *(ulonglong2*)&g_h1[gr * C1 + tc * 8]     = s0;
            *(ulonglong2*)&g_h1[gr * C1 + tc * 8 + 4] = s1;
        }
    }
}

// ---------------- attention logits layer 1 (warp per node) ----------------
__global__ void att1_kernel(const float* __restrict__ att_s, const float* __restrict__ att_d) {
    int gt = blockIdx.x * blockDim.x + threadIdx.x;
    int n = gt >> 5, lane = gt & 31;
    if (n >= NN) return;
    float4 h  = *(const float4*)&g_h1[n * C1 + lane * 4];
    float4 as = *(const float4*)&att_s[lane * 4];
    float4 ad = *(const float4*)&att_d[lane * 4];
    float ps = h.x * as.x + h.y * as.y + h.z * as.z + h.w * as.w;
    float pd = h.x * ad.x + h.y * ad.y + h.z * ad.z + h.w * ad.w;
    ps += __shfl_down_sync(0xffffffff, ps, 4);
    ps += __shfl_down_sync(0xffffffff, ps, 2);
    ps += __shfl_down_sync(0xffffffff, ps, 1);
    pd += __shfl_down_sync(0xffffffff, pd, 4);
    pd += __shfl_down_sync(0xffffffff, pd, 2);
    pd += __shfl_down_sync(0xffffffff, pd, 1);
    if ((lane & 7) == 0) {
        int hi = lane >> 3;
        g_als1[n * HEADS + hi] = ps;
        g_ald1[n * HEADS + hi] = pd;
    }
}

// ---------------- layer-1 aggregation: warp per dst node, no atomics ----------------
// out1[d] = relu( (sum_e w_e * h1[src]) / (sum_e w_e) + b1 )
__global__ void agg1_kernel(const float* __restrict__ b1) {
    int gt = blockIdx.x * blockDim.x + threadIdx.x;
    int n = gt >> 5, lane = gt & 31;
    if (n >= NN) return;
    int h = lane >> 3;
    float ald = g_ald1[n * HEADS + h];
    int beg = g_rowptr[n], end = g_rowptr[n + 1];
    float4 acc = make_float4(0.f, 0.f, 0.f, 0.f);
    float den = 0.f;
    for (int i = beg; i < end; i++) {
        int s = __ldg(&g_csr_src[i]);
        float w = __expf(lrelu(__ldg(&g_als1[s * HEADS + h]) + ald));
        den += w;
        float4 hv = *(const float4*)&g_h1[s * C1 + lane * 4];
        acc.x += w * hv.x; acc.y += w * hv.y;
        acc.z += w * hv.z; acc.w += w * hv.w;
    }
    float inv = 1.f / (den + 1e-16f);
    float4 bb = *(const float4*)&b1[lane * 4];
    float4 o;
    o.x = fmaxf(acc.x * inv + bb.x, 0.f);
    o.y = fmaxf(acc.y * inv + bb.y, 0.f);
    o.z = fmaxf(acc.z * inv + bb.z, 0.f);
    o.w = fmaxf(acc.w * inv + bb.w, 0.f);
    *(float4*)&g_out1[n * C1 + lane * 4] = o;
}

// ---------------- GEMM2 + layer-2 logits (thread per node, f32x2) ----------------
__global__ __launch_bounds__(256) void l2gemm_kernel(const float* __restrict__ W2,
                                                     const float* __restrict__ as2,
                                                     const float* __restrict__ ad2) {
    __shared__ __align__(16) float W2s[FIN * CLS];
    __shared__ float s2s[CLS], d2s[CLS];
    int t = threadIdx.x;
    for (int i = t; i < FIN * CLS; i += 256) W2s[i] = W2[i];
    if (t < CLS) { s2s[t] = as2[t]; d2s[t] = ad2[t]; }
    __syncthreads();

    int n = blockIdx.x * blockDim.x + t;
    if (n >= NN) return;
    unsigned long long acc[20];
#pragma unroll
    for (int c = 0; c < 20; c++) acc[c] = 0ULL;

    for (int k = 0; k < FIN; k += 4) {
        float4 r4 = *(const float4*)&g_out1[n * FIN + k];
        float rv[4] = {r4.x, r4.y, r4.z, r4.w};
#pragma unroll
        for (int q = 0; q < 4; q++) {
            unsigned long long rp = pk2(rv[q], rv[q]);
            const float* wrow = &W2s[(k + q) * CLS];
#pragma unroll
            for (int c4 = 0; c4 < 10; c4++) {
                ulonglong2 wp = *(const ulonglong2*)&wrow[c4 * 4];
                fma2(acc[c4 * 2 + 0], rp, wp.x);
                fma2(acc[c4 * 2 + 1], rp, wp.y);
            }
        }
    }
    float ls = 0.f, ld = 0.f;
#pragma unroll
    for (int c2 = 0; c2 < 20; c2++) {
        unsigned int lo, hi;
        asm("mov.b64 {%0, %1}, %2;" : "=r"(lo), "=r"(hi) : "l"(acc[c2]));
        float v0 = __uint_as_float(lo), v1 = __uint_as_float(hi);
        g_h2[n * CLS + c2 * 2 + 0] = v0;
        g_h2[n * CLS + c2 * 2 + 1] = v1;
        ls += v0 * s2s[c2 * 2] + v1 * s2s[c2 * 2 + 1];
        ld += v0 * d2s[c2 * 2] + v1 * d2s[c2 * 2 + 1];
    }
    g_als2[n] = ls;
    g_ald2[n] = ld;
}

// ---------------- layer-2 aggregation + bias + log_softmax (warp per node) ----------------
__global__ void agg2_kernel(const float* __restrict__ b2, float* __restrict__ out) {
    int gt = blockIdx.x * blockDim.x + threadIdx.x;
    int n = gt >> 5, lane = gt & 31;
    if (n >= NN) return;
    float ald = g_ald2[n];
    int beg = g_rowptr[n], end = g_rowptr[n + 1];
    bool act = lane < 10;
    float4 acc = make_float4(0.f, 0.f, 0.f, 0.f);
    float den = 0.f;
    for (int i = beg; i < end; i++) {
        int s = __ldg(&g_csr_src[i]);
        float w = __expf(lrelu(__ldg(&g_als2[s]) + ald));
        den += w;
        if (act) {
            float4 hv = *(const float4*)&g_h2[s * CLS + lane * 4];
            acc.x += w * hv.x; acc.y += w * hv.y;
            acc.z += w * hv.z; acc.w += w * hv.w;
        }
    }
    float inv = 1.f / (den + 1e-16f);
    float4 v = make_float4(-1e30f, -1e30f, -1e30f, -1e30f);
    if (act) {
        float4 bb = *(const float4*)&b2[lane * 4];
        v.x = acc.x * inv + bb.x;
        v.y = acc.y * inv + bb.y;
        v.z = acc.z * inv + bb.z;
        v.w = acc.w * inv + bb.w;
    }
    float m = fmaxf(fmaxf(v.x, v.y), fmaxf(v.z, v.w));
#pragma unroll
    for (int o = 16; o > 0; o >>= 1) m = fmaxf(m, __shfl_xor_sync(0xffffffff, m, o));
    float s4 = 0.f;
    if (act)
        s4 = __expf(v.x - m) + __expf(v.y - m) + __expf(v.z - m) + __expf(v.w - m);
#pragma unroll
    for (int o = 16; o > 0; o >>= 1) s4 += __shfl_xor_sync(0xffffffff, s4, o);
    float lse = m + logf(s4);
    if (act) {
        float4 r;
        r.x = v.x - lse; r.y = v.y - lse; r.z = v.z - lse; r.w = v.w - lse;
        *(float4*)&out[n * CLS + lane * 4] = r;
    }
}

// ---------------- launch ----------------
extern "C" void kernel_launch(void* const* d_in, const int* in_sizes, int n_in,
                              void* d_out, int out_size) {
    const float* x   = (const float*)d_in[0];
    const int*   ei  = (const int*)  d_in[1];
    const float* W1  = (const float*)d_in[2];
    const float* as1 = (const float*)d_in[3];
    const float* ad1 = (const float*)d_in[4];
    const float* b1  = (const float*)d_in[5];
    const float* W2  = (const float*)d_in[6];
    const float* as2 = (const float*)d_in[7];
    const float* ad2 = (const float*)d_in[8];
    const float* b2  = (const float*)d_in[9];
    float* out = (float*)d_out;

    zero_cnt_kernel<<<(NN + 255) / 256, 256>>>();
    hist_kernel<<<(TOTE + 255) / 256, 256>>>(ei);
    scan_kernel<<<1, 1024>>>();
    scatter_kernel<<<(TOTE + 255) / 256, 256>>>(ei);
    gemm1_kernel<<<(NN + 127) / 128, 256>>>(x, W1);
    att1_kernel<<<(NN * 32 + 255) / 256, 256>>>(as1, ad1);
    agg1_kernel<<<(NN * 32 + 255) / 256, 256>>>(b1);
    l2gemm_kernel<<<(NN + 255) / 256, 256>>>(W2, as2, ad2);
    agg2_kernel<<<(NN * 32 + 255) / 256, 256>>>(b2, out);
}

// round 5
// speedup vs baseline: 1.1214x; 1.0034x over previous
#include <cuda_runtime.h>
#include <math.h>

#define NN    50000
#define FIN   128
#define C1    128
#define HEADS 4
#define HID   32
#define CLS   40
#define EE    800000
#define TOTE  (EE + NN)
#define NEG   0.2f

// ---------------- scratch ----------------
__device__ float g_h1  [NN * C1];
__device__ float g_out1[NN * C1];
__device__ float g_als1[NN * HEADS];
__device__ float g_ald1[NN * HEADS];
__device__ float g_h2  [NN * CLS];
__device__ float g_als2[NN];
__device__ float g_ald2[NN];
__device__ int   g_cnt [NN];
__device__ int   g_rowptr[NN + 1];
__device__ int   g_csr_src[TOTE];

__device__ __forceinline__ float lrelu(float x) { return x > 0.f ? x : NEG * x; }

__device__ __forceinline__ unsigned long long pk2(float a, float b) {
    unsigned long long r;
    asm("mov.b64 %0, {%1, %2};" : "=l"(r)
        : "r"(__float_as_uint(a)), "r"(__float_as_uint(b)));
    return r;
}
__device__ __forceinline__ void fma2(unsigned long long& d,
                                     unsigned long long a, unsigned long long b) {
    asm("fma.rn.f32x2 %0, %1, %2, %0;" : "+l"(d) : "l"(a), "l"(b));
}
__device__ __forceinline__ float2 up2(unsigned long long p) {
    unsigned int lo, hi;
    asm("mov.b64 {%0, %1}, %2;" : "=r"(lo), "=r"(hi) : "l"(p));
    return make_float2(__uint_as_float(lo), __uint_as_float(hi));
}

// ---------------- CSR build ----------------
__global__ void zero_cnt_kernel() {
    int i = blockIdx.x * blockDim.x + threadIdx.x;
    if (i < NN) g_cnt[i] = 0;
}
// 4 edges per thread: independent atomic chains (latency-bound -> 4x MLP)
__global__ void hist_kernel(const int* __restrict__ ei) {
    int q = (blockIdx.x * blockDim.x + threadIdx.x) * 4;
    if (q >= TOTE) return;
    if (q + 4 <= EE) {
        int4 d4 = *(const int4*)&ei[EE + q];
        atomicAdd(&g_cnt[d4.x], 1);
        atomicAdd(&g_cnt[d4.y], 1);
        atomicAdd(&g_cnt[d4.z], 1);
        atomicAdd(&g_cnt[d4.w], 1);
    } else {
        for (int j = 0; j < 4 && q + j < TOTE; j++) {
            int e = q + j;
            int d = (e < EE) ? ei[EE + e] : e - EE;
            atomicAdd(&g_cnt[d], 1);
        }
    }
}
__global__ void scan_kernel() {
    __shared__ int sums[1024];
    const int CH = 49;
    int tid = threadIdx.x;
    int base = tid * CH;
    int s = 0;
#pragma unroll 7
    for (int j = 0; j < CH; j++) { int idx = base + j; if (idx < NN) s += g_cnt[idx]; }
    sums[tid] = s;
    __syncthreads();
    for (int off = 1; off < 1024; off <<= 1) {
        int v = (tid >= off) ? sums[tid - off] : 0;
        __syncthreads();
        sums[tid] += v;
        __syncthreads();
    }
    int run = sums[tid] - s;
    for (int j = 0; j < CH; j++) {
        int idx = base + j;
        if (idx < NN) {
            int c = g_cnt[idx];
            g_rowptr[idx] = run;
            g_cnt[idx] = run;
            run += c;
        }
    }
    if (tid == 1023) g_rowptr[NN] = sums[tid];
}
__global__ void scatter_kernel(const int* __restrict__ ei) {
    int q = (blockIdx.x * blockDim.x + threadIdx.x) * 4;
    if (q >= TOTE) return;
    if (q + 4 <= EE) {
        int4 s4 = *(const int4*)&ei[q];
        int4 d4 = *(const int4*)&ei[EE + q];
        int p0 = atomicAdd(&g_cnt[d4.x], 1);
        int p1 = atomicAdd(&g_cnt[d4.y], 1);
        int p2 = atomicAdd(&g_cnt[d4.z], 1);
        int p3 = atomicAdd(&g_cnt[d4.w], 1);
        g_csr_src[p0] = s4.x;
        g_csr_src[p1] = s4.y;
        g_csr_src[p2] = s4.z;
        g_csr_src[p3] = s4.w;
    } else {
        for (int j = 0; j < 4 && q + j < TOTE; j++) {
            int e = q + j;
            int s, d;
            if (e < EE) { s = ei[e]; d = ei[EE + e]; } else { s = d = e - EE; }
            int pos = atomicAdd(&g_cnt[d], 1);
            g_csr_src[pos] = s;
        }
    }
}

// ---------------- GEMM1 + fused attention logits ----------------
__global__ __launch_bounds__(256, 2) void gemm1_kernel(const float* __restrict__ x,
                                                       const float* __restrict__ W,
                                                       const float* __restrict__ att_s,
                                                       const float* __restrict__ att_d) {
    __shared__ __align__(16) float xst[32][132];
    __shared__ __align__(16) float ws [32][128];
    __shared__ __align__(16) float ps_s[128][4];
    __shared__ __align__(16) float pd_s[128][4];
    int t = threadIdx.x;
    int row0 = blockIdx.x * 128;
    int tr = t & 15, tc = t >> 4;

    // zero logit accumulators (visible via the loop's syncthreads)
    if (t < 128) *(float4*)&ps_s[t][0] = make_float4(0.f, 0.f, 0.f, 0.f);
    else         *(float4*)&pd_s[t - 128][0] = make_float4(0.f, 0.f, 0.f, 0.f);

    unsigned long long acc[8][4];
#pragma unroll
    for (int r = 0; r < 8; r++)
#pragma unroll
        for (int c = 0; c < 4; c++) acc[r][c] = 0ULL;

    for (int k0 = 0; k0 < FIN; k0 += 32) {
#pragma unroll
        for (int j = 0; j < 4; j++) {
            int idx = t + 256 * j;
            int r = idx >> 3, kq = idx & 7;
            int gr = row0 + r;
            float4 v = make_float4(0.f, 0.f, 0.f, 0.f);
            if (gr < NN) v = *(const float4*)&x[gr * FIN + k0 + kq * 4];
            xst[kq * 4 + 0][r] = v.x;
            xst[kq * 4 + 1][r] = v.y;
            xst[kq * 4 + 2][r] = v.z;
            xst[kq * 4 + 3][r] = v.w;
        }
#pragma unroll
        for (int j = 0; j < 4; j++) {
            int idx = t + 256 * j;
            int kk = idx >> 5, c4 = idx & 31;
            *(float4*)&ws[kk][c4 * 4] = *(const float4*)&W[(k0 + kk) * C1 + c4 * 4];
        }
        __syncthreads();
#pragma unroll 4
        for (int kk = 0; kk < 32; kk++) {
            float4 a0 = *(float4*)&xst[kk][tr * 8];
            float4 a1 = *(float4*)&xst[kk][tr * 8 + 4];
            ulonglong2 b0 = *(ulonglong2*)&ws[kk][tc * 8];
            ulonglong2 b1 = *(ulonglong2*)&ws[kk][tc * 8 + 4];
            float av[8] = {a0.x, a0.y, a0.z, a0.w, a1.x, a1.y, a1.z, a1.w};
#pragma unroll
            for (int r = 0; r < 8; r++) {
                unsigned long long ap = pk2(av[r], av[r]);
                fma2(acc[r][0], ap, b0.x);
                fma2(acc[r][1], ap, b0.y);
                fma2(acc[r][2], ap, b1.x);
                fma2(acc[r][3], ap, b1.y);
            }
        }
        __syncthreads();
    }

    // epilogue: store h1 + per-head logit partials
    float4 as0 = *(const float4*)&att_s[tc * 8];
    float4 as1 = *(const float4*)&att_s[tc * 8 + 4];
    float4 ad0 = *(const float4*)&att_d[tc * 8];
    float4 ad1 = *(const float4*)&att_d[tc * 8 + 4];
    int hd = tc >> 2;                 // this thread's 8 cols lie in head tc/4
#pragma unroll
    for (int r = 0; r < 8; r++) {
        int row = tr * 8 + r;
        int gr = row0 + row;
        float2 v0 = up2(acc[r][0]), v1 = up2(acc[r][1]);
        float2 v2 = up2(acc[r][2]), v3 = up2(acc[r][3]);
        float ps = v0.x * as0.x + v0.y * as0.y + v1.x * as0.z + v1.y * as0.w
                 + v2.x * as1.x + v2.y * as1.y + v3.x * as1.z + v3.y * as1.w;
        float pd = v0.x * ad0.x + v0.y * ad0.y + v1.x * ad0.z + v1.y * ad0.w
                 + v2.x * ad1.x + v2.y * ad1.y + v3.x * ad1.z + v3.y * ad1.w;
        atomicAdd(&ps_s[row][hd], ps);
        atomicAdd(&pd_s[row][hd], pd);
        if (gr < NN) {
            ulonglong2 s0; s0.x = acc[r][0]; s0.y = acc[r][1];
            ulonglong2 s1; s1.x = acc[r][2]; s1.y = acc[r][3];
            *(ulonglong2*)&g_h1[gr * C1 + tc * 8]     = s0;
            *(ulonglong2*)&g_h1[gr * C1 + tc * 8 + 4] = s1;
        }
    }
    __syncthreads();
    if (t < 128) {
        int gr = row0 + t;
        if (gr < NN) *(float4*)&g_als1[gr * HEADS] = *(float4*)&ps_s[t][0];
    } else {
        int rr = t - 128;
        int gr = row0 + rr;
        if (gr < NN) *(float4*)&g_ald1[gr * HEADS] = *(float4*)&pd_s[rr][0];
    }
}

// ---------------- layer-1 aggregation (warp/node, 2-edge pipeline) ----------------
__global__ void agg1_kernel(const float* __restrict__ b1) {
    int gt = blockIdx.x * blockDim.x + threadIdx.x;
    int n = gt >> 5, lane = gt & 31;
    if (n >= NN) return;
    int h = lane >> 3;
    float ald = g_ald1[n * HEADS + h];
    int beg = g_rowptr[n], end = g_rowptr[n + 1];
    float4 acc = make_float4(0.f, 0.f, 0.f, 0.f);
    float den = 0.f;
    int i = beg;
    for (; i + 1 < end; i += 2) {
        int sA = __ldg(&g_csr_src[i]);
        int sB = __ldg(&g_csr_src[i + 1]);
        float aA = __ldg(&g_als1[sA * HEADS + h]);
        float aB = __ldg(&g_als1[sB * HEADS + h]);
        float4 hA = *(const float4*)&g_h1[sA * C1 + lane * 4];
        float4 hB = *(const float4*)&g_h1[sB * C1 + lane * 4];
        float wA = __expf(lrelu(aA + ald));
        float wB = __expf(lrelu(aB + ald));
        den += wA + wB;
        acc.x += wA * hA.x + wB * hB.x;
        acc.y += wA * hA.y + wB * hB.y;
        acc.z += wA * hA.z + wB * hB.z;
        acc.w += wA * hA.w + wB * hB.w;
    }
    if (i < end) {
        int s = __ldg(&g_csr_src[i]);
        float w = __expf(lrelu(__ldg(&g_als1[s * HEADS + h]) + ald));
        den += w;
        float4 hv = *(const float4*)&g_h1[s * C1 + lane * 4];
        acc.x += w * hv.x; acc.y += w * hv.y;
        acc.z += w * hv.z; acc.w += w * hv.w;
    }
    float inv = 1.f / (den + 1e-16f);
    float4 bb = *(const float4*)&b1[lane * 4];
    float4 o;
    o.x = fmaxf(acc.x * inv + bb.x, 0.f);
    o.y = fmaxf(acc.y * inv + bb.y, 0.f);
    o.z = fmaxf(acc.z * inv + bb.z, 0.f);
    o.w = fmaxf(acc.w * inv + bb.w, 0.f);
    *(float4*)&g_out1[n * C1 + lane * 4] = o;
}

// ---------------- GEMM2 + layer-2 logits ----------------
__global__ __launch_bounds__(256) void l2gemm_kernel(const float* __restrict__ W2,
                                                     const float* __restrict__ as2,
                                                     const float* __restrict__ ad2) {
    __shared__ __align__(16) float W2s[FIN * CLS];
    __shared__ float s2s[CLS], d2s[CLS];
    int t = threadIdx.x;
    for (int i = t; i < FIN * CLS; i += 256) W2s[i] = W2[i];
    if (t < CLS) { s2s[t] = as2[t]; d2s[t] = ad2[t]; }
    __syncthreads();

    int n = blockIdx.x * blockDim.x + t;
    if (n >= NN) return;
    unsigned long long acc[20];
#pragma unroll
    for (int c = 0; c < 20; c++) acc[c] = 0ULL;

    for (int k = 0; k < FIN; k += 4) {
        float4 r4 = *(const float4*)&g_out1[n * FIN + k];
        float rv[4] = {r4.x, r4.y, r4.z, r4.w};
#pragma unroll
        for (int q = 0; q < 4; q++) {
            unsigned long long rp = pk2(rv[q], rv[q]);
            const float* wrow = &W2s[(k + q) * CLS];
#pragma unroll
            for (int c4 = 0; c4 < 10; c4++) {
                ulonglong2 wp = *(const ulonglong2*)&wrow[c4 * 4];
                fma2(acc[c4 * 2 + 0], rp, wp.x);
                fma2(acc[c4 * 2 + 1], rp, wp.y);
            }
        }
    }
    float ls = 0.f, ld = 0.f;
#pragma unroll
    for (int c2 = 0; c2 < 20; c2++) {
        float2 v = up2(acc[c2]);
        g_h2[n * CLS + c2 * 2 + 0] = v.x;
        g_h2[n * CLS + c2 * 2 + 1] = v.y;
        ls += v.x * s2s[c2 * 2] + v.y * s2s[c2 * 2 + 1];
        ld += v.x * d2s[c2 * 2] + v.y * d2s[c2 * 2 + 1];
    }
    g_als2[n] = ls;
    g_ald2[n] = ld;
}

// ---------------- layer-2 aggregation + bias + log_softmax ----------------
__global__ void agg2_kernel(const float* __restrict__ b2, float* __restrict__ out) {
    int gt = blockIdx.x * blockDim.x + threadIdx.x;
    int n = gt >> 5, lane = gt & 31;
    if (n >= NN) return;
    float ald = g_ald2[n];
    int beg = g_rowptr[n], end = g_rowptr[n + 1];
    bool act = lane < 10;
    float4 acc = make_float4(0.f, 0.f, 0.f, 0.f);
    float den = 0.f;
    int i = beg;
    for (; i + 1 < end; i += 2) {
        int sA = __ldg(&g_csr_src[i]);
        int sB = __ldg(&g_csr_src[i + 1]);
        float aA = __ldg(&g_als2[sA]);
        float aB = __ldg(&g_als2[sB]);
        float4 hA = make_float4(0.f, 0.f, 0.f, 0.f);
        float4 hB = make_float4(0.f, 0.f, 0.f, 0.f);
        if (act) {
            hA = *(const float4*)&g_h2[sA * CLS + lane * 4];
            hB = *(const float4*)&g_h2[sB * CLS + lane * 4];
        }
        float wA = __expf(lrelu(aA + ald));
        float wB = __expf(lrelu(aB + ald));
        den += wA + wB;
        acc.x += wA * hA.x + wB * hB.x;
        acc.y += wA * hA.y + wB * hB.y;
        acc.z += wA * hA.z + wB * hB.z;
        acc.w += wA * hA.w + wB * hB.w;
    }
    if (i < end) {
        int s = __ldg(&g_csr_src[i]);
        float w = __expf(lrelu(__ldg(&g_als2[s]) + ald));
        den += w;
        if (act) {
            float4 hv = *(const float4*)&g_h2[s * CLS + lane * 4];
            acc.x += w * hv.x; acc.y += w * hv.y;
            acc.z += w * hv.z; acc.w += w * hv.w;
        }
    }
    float inv = 1.f / (den + 1e-16f);
    float4 v = make_float4(-1e30f, -1e30f, -1e30f, -1e30f);
    if (act) {
        float4 bb = *(const float4*)&b2[lane * 4];
        v.x = acc.x * inv + bb.x;
        v.y = acc.y * inv + bb.y;
        v.z = acc.z * inv + bb.z;
        v.w = acc.w * inv + bb.w;
    }
    float m = fmaxf(fmaxf(v.x, v.y), fmaxf(v.z, v.w));
#pragma unroll
    for (int o = 16; o > 0; o >>= 1) m = fmaxf(m, __shfl_xor_sync(0xffffffff, m, o));
    float s4 = 0.f;
    if (act)
        s4 = __expf(v.x - m) + __expf(v.y - m) + __expf(v.z - m) + __expf(v.w - m);
#pragma unroll
    for (int o = 16; o > 0; o >>= 1) s4 += __shfl_xor_sync(0xffffffff, s4, o);
    float lse = m + logf(s4);
    if (act) {
        float4 r;
        r.x = v.x - lse; r.y = v.y - lse; r.z = v.z - lse; r.w = v.w - lse;
        *(float4*)&out[n * CLS + lane * 4] = r;
    }
}

// ---------------- launch: fork CSR build onto a side stream ----------------
extern "C" void kernel_launch(void* const* d_in, const int* in_sizes, int n_in,
                              void* d_out, int out_size) {
    const float* x   = (const float*)d_in[0];
    const int*   ei  = (const int*)  d_in[1];
    const float* W1  = (const float*)d_in[2];
    const float* as1 = (const float*)d_in[3];
    const float* ad1 = (const float*)d_in[4];
    const float* b1  = (const float*)d_in[5];
    const float* W2  = (const float*)d_in[6];
    const float* as2 = (const float*)d_in[7];
    const float* ad2 = (const float*)d_in[8];
    const float* b2  = (const float*)d_in[9];
    float* out = (float*)d_out;

    // kernel_launch is called only a bounded number of times (correctness +
    // capture); stream/event creation is capture-legal and touches no device mem.
    cudaStream_t s2;
    cudaEvent_t evA, evB;
    cudaStreamCreateWithFlags(&s2, cudaStreamNonBlocking);
    cudaEventCreateWithFlags(&evA, cudaEventDisableTiming);
    cudaEventCreateWithFlags(&evB, cudaEventDisableTiming);

    cudaEventRecord(evA, 0);
    cudaStreamWaitEvent(s2, evA, 0);

    // branch A (side stream): CSR build
    zero_cnt_kernel<<<(NN + 255) / 256, 256, 0, s2>>>();
    hist_kernel<<<((TOTE + 3) / 4 + 255) / 256, 256, 0, s2>>>(ei);
    scan_kernel<<<1, 1024, 0, s2>>>();
    scatter_kernel<<<((TOTE + 3) / 4 + 255) / 256, 256, 0, s2>>>(ei);
    cudaEventRecord(evB, s2);

    // branch B (main stream): dense layer 1 + fused attention logits
    gemm1_kernel<<<(NN + 127) / 128, 256>>>(x, W1, as1, ad1);

    // join
    cudaStreamWaitEvent(0, evB, 0);

    agg1_kernel<<<(NN * 32 + 255) / 256, 256>>>(b1);
    l2gemm_kernel<<<(NN + 255) / 256, 256>>>(W2, as2, ad2);
    agg2_kernel<<<(NN * 32 + 255) / 256, 256>>>(b2, out);
}

// round 7
// speedup vs baseline: 1.1954x; 1.0660x over previous
#include <cuda_runtime.h>
#include <cuda_fp16.h>
#include <math.h>

#define NN    50000
#define FIN   128
#define C1    128
#define HEADS 4
#define HID   32
#define CLS   40
#define EE    800000
#define TOTE  (EE + NN)
#define NEG   0.2f

// ---------------- scratch ----------------
__device__ __half g_h1h[NN * C1];      // layer-1 features, fp16
__device__ float  g_out1[NN * C1];     // relu(agg + b1), fp32
__device__ __half g_h2h[NN * CLS];     // layer-2 features, fp16
__device__ float  g_als1[NN * HEADS];
__device__ float  g_ald1[NN * HEADS];
__device__ float  g_als2[NN];
__device__ float  g_ald2[NN];
__device__ int    g_cnt [NN];
__device__ int    g_rowptr[NN + 1];
__device__ int    g_csr_src[TOTE];

__device__ __forceinline__ float lrelu(float x) { return x > 0.f ? x : NEG * x; }

__device__ __forceinline__ unsigned long long pk2(float a, float b) {
    unsigned long long r;
    asm("mov.b64 %0, {%1, %2};" : "=l"(r)
        : "r"(__float_as_uint(a)), "r"(__float_as_uint(b)));
    return r;
}
__device__ __forceinline__ void fma2(unsigned long long& d,
                                     unsigned long long a, unsigned long long b) {
    asm("fma.rn.f32x2 %0, %1, %2, %0;" : "+l"(d) : "l"(a), "l"(b));
}
__device__ __forceinline__ float2 up2(unsigned long long p) {
    unsigned int lo, hi;
    asm("mov.b64 {%0, %1}, %2;" : "=r"(lo), "=r"(hi) : "l"(p));
    return make_float2(__uint_as_float(lo), __uint_as_float(hi));
}
__device__ __forceinline__ float2 h2f(unsigned int u) {
    __half2 h = *reinterpret_cast<__half2*>(&u);
    return __half22float2(h);
}
__device__ __forceinline__ unsigned int f2h(float a, float b) {
    __half2 h = __float22half2_rn(make_float2(a, b));
    return *reinterpret_cast<unsigned int*>(&h);
}

// ---------------- CSR build ----------------
// hist: no-return reduction (REDG), 4 edges/thread
__global__ void hist_kernel(const int* __restrict__ ei) {
    int q = (blockIdx.x * blockDim.x + threadIdx.x) * 4;
    if (q >= TOTE) return;
    if (q + 4 <= EE) {
        int4 d4 = *(const int4*)&ei[EE + q];
        asm volatile("red.global.add.u32 [%0], %1;" :: "l"(&g_cnt[d4.x]), "r"(1) : "memory");
        asm volatile("red.global.add.u32 [%0], %1;" :: "l"(&g_cnt[d4.y]), "r"(1) : "memory");
        asm volatile("red.global.add.u32 [%0], %1;" :: "l"(&g_cnt[d4.z]), "r"(1) : "memory");
        asm volatile("red.global.add.u32 [%0], %1;" :: "l"(&g_cnt[d4.w]), "r"(1) : "memory");
    } else {
        for (int j = 0; j < 4 && q + j < TOTE; j++) {
            int e = q + j;
            int d = (e < EE) ? ei[EE + e] : e - EE;
            asm volatile("red.global.add.u32 [%0], %1;" :: "l"(&g_cnt[d]), "r"(1) : "memory");
        }
    }
}
__global__ void scan_kernel() {
    __shared__ int sums[1024];
    const int CH = 49;
    int tid = threadIdx.x;
    int base = tid * CH;
    int s = 0;
#pragma unroll 7
    for (int j = 0; j < CH; j++) { int idx = base + j; if (idx < NN) s += g_cnt[idx]; }
    sums[tid] = s;
    __syncthreads();
    for (int off = 1; off < 1024; off <<= 1) {
        int v = (tid >= off) ? sums[tid - off] : 0;
        __syncthreads();
        sums[tid] += v;
        __syncthreads();
    }
    int run = sums[tid] - s;
    for (int j = 0; j < CH; j++) {
        int idx = base + j;
        if (idx < NN) {
            int c = g_cnt[idx];
            g_rowptr[idx] = run;
            g_cnt[idx] = run;
            run += c;
        }
    }
    if (tid == 1023) g_rowptr[NN] = sums[tid];
}
__global__ void scatter_kernel(const int* __restrict__ ei) {
    int q = (blockIdx.x * blockDim.x + threadIdx.x) * 4;
    if (q >= TOTE) return;
    if (q + 4 <= EE) {
        int4 s4 = *(const int4*)&ei[q];
        int4 d4 = *(const int4*)&ei[EE + q];
        int p0 = atomicAdd(&g_cnt[d4.x], 1);
        int p1 = atomicAdd(&g_cnt[d4.y], 1);
        int p2 = atomicAdd(&g_cnt[d4.z], 1);
        int p3 = atomicAdd(&g_cnt[d4.w], 1);
        g_csr_src[p0] = s4.x;
        g_csr_src[p1] = s4.y;
        g_csr_src[p2] = s4.z;
        g_csr_src[p3] = s4.w;
    } else {
        for (int j = 0; j < 4 && q + j < TOTE; j++) {
            int e = q + j;
            int s, d;
            if (e < EE) { s = ei[e]; d = ei[EE + e]; } else { s = d = e - EE; }
            int pos = atomicAdd(&g_cnt[d], 1);
            g_csr_src[pos] = s;
        }
    }
}

// ---------------- GEMM1 + fused attention logits (h1 stored fp16) ----------------
__global__ __launch_bounds__(256, 2) void gemm1_kernel(const float* __restrict__ x,
                                                       const float* __restrict__ W,
                                                       const float* __restrict__ att_s,
                                                       const float* __restrict__ att_d) {
    __shared__ __align__(16) float xst[32][132];
    __shared__ __align__(16) float ws [32][128];
    __shared__ __align__(16) float ps_s[128][4];
    __shared__ __align__(16) float pd_s[128][4];
    int t = threadIdx.x;
    int row0 = blockIdx.x * 128;
    int tr = t & 15, tc = t >> 4;

    if (t < 128) *(float4*)&ps_s[t][0] = make_float4(0.f, 0.f, 0.f, 0.f);
    else         *(float4*)&pd_s[t - 128][0] = make_float4(0.f, 0.f, 0.f, 0.f);

    unsigned long long acc[8][4];
#pragma unroll
    for (int r = 0; r < 8; r++)
#pragma unroll
        for (int c = 0; c < 4; c++) acc[r][c] = 0ULL;

    for (int k0 = 0; k0 < FIN; k0 += 32) {
#pragma unroll
        for (int j = 0; j < 4; j++) {
            int idx = t + 256 * j;
            int r = idx >> 3, kq = idx & 7;
            int gr = row0 + r;
            float4 v = make_float4(0.f, 0.f, 0.f, 0.f);
            if (gr < NN) v = *(const float4*)&x[gr * FIN + k0 + kq * 4];
            xst[kq * 4 + 0][r] = v.x;
            xst[kq * 4 + 1][r] = v.y;
            xst[kq * 4 + 2][r] = v.z;
            xst[kq * 4 + 3][r] = v.w;
        }
#pragma unroll
        for (int j = 0; j < 4; j++) {
            int idx = t + 256 * j;
            int kk = idx >> 5, c4 = idx & 31;
            *(float4*)&ws[kk][c4 * 4] = *(const float4*)&W[(k0 + kk) * C1 + c4 * 4];
        }
        __syncthreads();
#pragma unroll 4
        for (int kk = 0; kk < 32; kk++) {
            float4 a0 = *(float4*)&xst[kk][tr * 8];
            float4 a1 = *(float4*)&xst[kk][tr * 8 + 4];
            ulonglong2 b0 = *(ulonglong2*)&ws[kk][tc * 8];
            ulonglong2 b1 = *(ulonglong2*)&ws[kk][tc * 8 + 4];
            float av[8] = {a0.x, a0.y, a0.z, a0.w, a1.x, a1.y, a1.z, a1.w};
#pragma unroll
            for (int r = 0; r < 8; r++) {
                unsigned long long ap = pk2(av[r], av[r]);
                fma2(acc[r][0], ap, b0.x);
                fma2(acc[r][1], ap, b0.y);
                fma2(acc[r][2], ap, b1.x);
                fma2(acc[r][3], ap, b1.y);
            }
        }
        __syncthreads();
    }

    float4 as0 = *(const float4*)&att_s[tc * 8];
    float4 as1 = *(const float4*)&att_s[tc * 8 + 4];
    float4 ad0 = *(const float4*)&att_d[tc * 8];
    float4 ad1 = *(const float4*)&att_d[tc * 8 + 4];
    int hd = tc >> 2;
#pragma unroll
    for (int r = 0; r < 8; r++) {
        int row = tr * 8 + r;
        int gr = row0 + row;
        float2 v0 = up2(acc[r][0]), v1 = up2(acc[r][1]);
        float2 v2 = up2(acc[r][2]), v3 = up2(acc[r][3]);
        float ps = v0.x * as0.x + v0.y * as0.y + v1.x * as0.z + v1.y * as0.w
                 + v2.x * as1.x + v2.y * as1.y + v3.x * as1.z + v3.y * as1.w;
        float pd = v0.x * ad0.x + v0.y * ad0.y + v1.x * ad0.z + v1.y * ad0.w
                 + v2.x * ad1.x + v2.y * ad1.y + v3.x * ad1.z + v3.y * ad1.w;
        atomicAdd(&ps_s[row][hd], ps);
        atomicAdd(&pd_s[row][hd], pd);
        if (gr < NN) {
            uint4 st;
            st.x = f2h(v0.x, v0.y);
            st.y = f2h(v1.x, v1.y);
            st.z = f2h(v2.x, v2.y);
            st.w = f2h(v3.x, v3.y);
            *(uint4*)&g_h1h[gr * C1 + tc * 8] = st;
        }
    }
    __syncthreads();
    if (t < 128) {
        int gr = row0 + t;
        if (gr < NN) *(float4*)&g_als1[gr * HEADS] = *(float4*)&ps_s[t][0];
    } else {
        int rr = t - 128;
        int gr = row0 + rr;
        if (gr < NN) *(float4*)&g_ald1[gr * HEADS] = *(float4*)&pd_s[rr][0];
    }
}

// ---------------- layer-1 aggregation: warp/node, fp16 gather, 4-edge batches ----------------
__global__ void agg1_kernel(const float* __restrict__ b1) {
    int gt = blockIdx.x * blockDim.x + threadIdx.x;
    int n = gt >> 5, lane = gt & 31;
    if (n >= NN) return;
    int h = lane >> 3;
    float ald = g_ald1[n * HEADS + h];
    int beg = g_rowptr[n], end = g_rowptr[n + 1];
    float4 acc = make_float4(0.f, 0.f, 0.f, 0.f);
    float den = 0.f;
    int i = beg;
    for (; i + 4 <= end; i += 4) {
        int sA = __ldg(&g_csr_src[i]);
        int sB = __ldg(&g_csr_src[i + 1]);
        int sC = __ldg(&g_csr_src[i + 2]);
        int sD = __ldg(&g_csr_src[i + 3]);
        float aA = __ldg(&g_als1[sA * HEADS + h]);
        float aB = __ldg(&g_als1[sB * HEADS + h]);
        float aC = __ldg(&g_als1[sC * HEADS + h]);
        float aD = __ldg(&g_als1[sD * HEADS + h]);
        uint2 rA = *(const uint2*)&g_h1h[sA * C1 + lane * 4];
        uint2 rB = *(const uint2*)&g_h1h[sB * C1 + lane * 4];
        uint2 rC = *(const uint2*)&g_h1h[sC * C1 + lane * 4];
        uint2 rD = *(const uint2*)&g_h1h[sD * C1 + lane * 4];
        float wA = __expf(lrelu(aA + ald));
        float wB = __expf(lrelu(aB + ald));
        float wC = __expf(lrelu(aC + ald));
        float wD = __expf(lrelu(aD + ald));
        den += (wA + wB) + (wC + wD);
        float2 A0 = h2f(rA.x), A1 = h2f(rA.y);
        float2 B0 = h2f(rB.x), B1 = h2f(rB.y);
        float2 C0 = h2f(rC.x), C1v = h2f(rC.y);
        float2 D0 = h2f(rD.x), D1 = h2f(rD.y);
        acc.x += wA * A0.x + wB * B0.x + wC * C0.x + wD * D0.x;
        acc.y += wA * A0.y + wB * B0.y + wC * C0.y + wD * D0.y;
        acc.z += wA * A1.x + wB * B1.x + wC * C1v.x + wD * D1.x;
        acc.w += wA * A1.y + wB * B1.y + wC * C1v.y + wD * D1.y;
    }
    for (; i < end; i++) {
        int s = __ldg(&g_csr_src[i]);
        float w = __expf(lrelu(__ldg(&g_als1[s * HEADS + h]) + ald));
        den += w;
        uint2 r = *(const uint2*)&g_h1h[s * C1 + lane * 4];
        float2 p0 = h2f(r.x), p1 = h2f(r.y);
        acc.x += w * p0.x; acc.y += w * p0.y;
        acc.z += w * p1.x; acc.w += w * p1.y;
    }
    float inv = 1.f / (den + 1e-16f);
    float4 bb = *(const float4*)&b1[lane * 4];
    float4 o;
    o.x = fmaxf(acc.x * inv + bb.x, 0.f);
    o.y = fmaxf(acc.y * inv + bb.y, 0.f);
    o.z = fmaxf(acc.z * inv + bb.z, 0.f);
    o.w = fmaxf(acc.w * inv + bb.w, 0.f);
    *(float4*)&g_out1[n * C1 + lane * 4] = o;
}

// ---------------- GEMM2 + layer-2 logits (h2 stored fp16) ----------------
__global__ __launch_bounds__(256) void l2gemm_kernel(const float* __restrict__ W2,
                                                     const float* __restrict__ as2,
                                                     const float* __restrict__ ad2) {
    __shared__ __align__(16) float W2s[FIN * CLS];
    __shared__ float s2s[CLS], d2s[CLS];
    int t = threadIdx.x;
    for (int i = t; i < FIN * CLS; i += 256) W2s[i] = W2[i];
    if (t < CLS) { s2s[t] = as2[t]; d2s[t] = ad2[t]; }
    __syncthreads();

    int n = blockIdx.x * blockDim.x + t;
    if (n >= NN) return;
    unsigned long long acc[20];
#pragma unroll
    for (int c = 0; c < 20; c++) acc[c] = 0ULL;

    for (int k = 0; k < FIN; k += 4) {
        float4 r4 = *(const float4*)&g_out1[n * FIN + k];
        float rv[4] = {r4.x, r4.y, r4.z, r4.w};
#pragma unroll
        for (int q = 0; q < 4; q++) {
            unsigned long long rp = pk2(rv[q], rv[q]);
            const float* wrow = &W2s[(k + q) * CLS];
#pragma unroll
            for (int c4 = 0; c4 < 10; c4++) {
                ulonglong2 wp = *(const ulonglong2*)&wrow[c4 * 4];
                fma2(acc[c4 * 2 + 0], rp, wp.x);
                fma2(acc[c4 * 2 + 1], rp, wp.y);
            }
        }
    }
    float ls = 0.f, ld = 0.f;
    unsigned int hp[20];
#pragma unroll
    for (int c2 = 0; c2 < 20; c2++) {
        float2 v = up2(acc[c2]);
        hp[c2] = f2h(v.x, v.y);
        ls += v.x * s2s[c2 * 2] + v.y * s2s[c2 * 2 + 1];
        ld += v.x * d2s[c2 * 2] + v.y * d2s[c2 * 2 + 1];
    }
    uint4* dst = (uint4*)&g_h2h[n * CLS];
#pragma unroll
    for (int j = 0; j < 5; j++) {
        uint4 u;
        u.x = hp[j * 4 + 0]; u.y = hp[j * 4 + 1];
        u.z = hp[j * 4 + 2]; u.w = hp[j * 4 + 3];
        dst[j] = u;
    }
    g_als2[n] = ls;
    g_ald2[n] = ld;
}

// ---------------- layer-2 aggregation + bias + log_softmax ----------------
__global__ void agg2_kernel(const float* __restrict__ b2, float* __restrict__ out) {
    int gt = blockIdx.x * blockDim.x + threadIdx.x;
    int n = gt >> 5, lane = gt & 31;
    if (n >= NN) return;
    float ald = g_ald2[n];
    int beg = g_rowptr[n], end = g_rowptr[n + 1];
    bool act = lane < 10;
    float4 acc = make_float4(0.f, 0.f, 0.f, 0.f);
    float den = 0.f;
    int i = beg;
    for (; i + 4 <= end; i += 4) {
        int sA = __ldg(&g_csr_src[i]);
        int sB = __ldg(&g_csr_src[i + 1]);
        int sC = __ldg(&g_csr_src[i + 2]);
        int sD = __ldg(&g_csr_src[i + 3]);
        float aA = __ldg(&g_als2[sA]);
        float aB = __ldg(&g_als2[sB]);
        float aC = __ldg(&g_als2[sC]);
        float aD = __ldg(&g_als2[sD]);
        uint2 rA = make_uint2(0u, 0u), rB = rA, rC = rA, rD = rA;
        if (act) {
            rA = *(const uint2*)&g_h2h[sA * CLS + lane * 4];
            rB = *(const uint2*)&g_h2h[sB * CLS + lane * 4];
            rC = *(const uint2*)&g_h2h[sC * CLS + lane * 4];
            rD = *(const uint2*)&g_h2h[sD * CLS + lane * 4];
        }
        float wA = __expf(lrelu(aA + ald));
        float wB = __expf(lrelu(aB + ald));
        float wC = __expf(lrelu(aC + ald));
        float wD = __expf(lrelu(aD + ald));
        den += (wA + wB) + (wC + wD);
        float2 A0 = h2f(rA.x), A1 = h2f(rA.y);
        float2 B0 = h2f(rB.x), B1 = h2f(rB.y);
        float2 C0 = h2f(rC.x), C1v = h2f(rC.y);
        float2 D0 = h2f(rD.x), D1 = h2f(rD.y);
        acc.x += wA * A0.x + wB * B0.x + wC * C0.x + wD * D0.x;
        acc.y += wA * A0.y + wB * B0.y + wC * C0.y + wD * D0.y;
        acc.z += wA * A1.x + wB * B1.x + wC * C1v.x + wD * D1.x;
        acc.w += wA * A1.y + wB * B1.y + wC * C1v.y + wD * D1.y;
    }
    for (; i < end; i++) {
        int s = __ldg(&g_csr_src[i]);
        float w = __expf(lrelu(__ldg(&g_als2[s]) + ald));
        den += w;
        if (act) {
            uint2 r = *(const uint2*)&g_h2h[s * CLS + lane * 4];
            float2 p0 = h2f(r.x), p1 = h2f(r.y);
            acc.x += w * p0.x; acc.y += w * p0.y;
            acc.z += w * p1.x; acc.w += w * p1.y;
        }
    }
    float inv = 1.f / (den + 1e-16f);
    float4 v = make_float4(-1e30f, -1e30f, -1e30f, -1e30f);
    if (act) {
        float4 bb = *(const float4*)&b2[lane * 4];
        v.x = acc.x * inv + bb.x;
        v.y = acc.y * inv + bb.y;
        v.z = acc.z * inv + bb.z;
        v.w = acc.w * inv + bb.w;
    }
    float m = fmaxf(fmaxf(v.x, v.y), fmaxf(v.z, v.w));
#pragma unroll
    for (int o = 16; o > 0; o >>= 1) m = fmaxf(m, __shfl_xor_sync(0xffffffff, m, o));
    float s4 = 0.f;
    if (act)
        s4 = __expf(v.x - m) + __expf(v.y - m) + __expf(v.z - m) + __expf(v.w - m);
#pragma unroll
    for (int o = 16; o > 0; o >>= 1) s4 += __shfl_xor_sync(0xffffffff, s4, o);
    float lse = m + logf(s4);
    if (act) {
        float4 r;
        r.x = v.x - lse; r.y = v.y - lse; r.z = v.z - lse; r.w = v.w - lse;
        *(float4*)&out[n * CLS + lane * 4] = r;
    }
}

// ---------------- launch ----------------
extern "C" void kernel_launch(void* const* d_in, const int* in_sizes, int n_in,
                              void* d_out, int out_size) {
    const float* x   = (const float*)d_in[0];
    const int*   ei  = (const int*)  d_in[1];
    const float* W1  = (const float*)d_in[2];
    const float* as1 = (const float*)d_in[3];
    const float* ad1 = (const float*)d_in[4];
    const float* b1  = (const float*)d_in[5];
    const float* W2  = (const float*)d_in[6];
    const float* as2 = (const float*)d_in[7];
    const float* ad2 = (const float*)d_in[8];
    const float* b2  = (const float*)d_in[9];
    float* out = (float*)d_out;

    cudaStream_t s2;
    cudaEvent_t evA, evB;
    cudaStreamCreateWithFlags(&s2, cudaStreamNonBlocking);
    cudaEventCreateWithFlags(&evA, cudaEventDisableTiming);
    cudaEventCreateWithFlags(&evB, cudaEventDisableTiming);

    cudaEventRecord(evA, 0);
    cudaStreamWaitEvent(s2, evA, 0);

    // branch A: CSR build
    void* cnt_ptr = nullptr;
    cudaGetSymbolAddress(&cnt_ptr, g_cnt);
    cudaMemsetAsync(cnt_ptr, 0, NN * sizeof(int), s2);
    hist_kernel<<<((TOTE + 3) / 4 + 255) / 256, 256, 0, s2>>>(ei);
    scan_kernel<<<1, 1024, 0, s2>>>();
    scatter_kernel<<<((TOTE + 3) / 4 + 255) / 256, 256, 0, s2>>>(ei);
    cudaEventRecord(evB, s2);

    // branch B: dense layer 1 + fused logits
    gemm1_kernel<<<(NN + 127) / 128, 256>>>(x, W1, as1, ad1);

    cudaStreamWaitEvent(0, evB, 0);

    agg1_kernel<<<(NN * 32 + 255) / 256, 256>>>(b1);
    l2gemm_kernel<<<(NN + 255) / 256, 256>>>(W2, as2, ad2);
    agg2_kernel<<<(NN * 32 + 255) / 256, 256>>>(b2, out);
}

// round 8
// speedup vs baseline: 1.3212x; 1.1053x over previous
#include <cuda_runtime.h>
#include <cuda_fp16.h>
#include <math.h>

#define NN    50000
#define FIN   128
#define C1    128
#define HEADS 4
#define HID   32
#define CLS   40
#define EE    800000
#define TOTE  (EE + NN)
#define NEG   0.2f

// ---------------- scratch ----------------
__device__ __half g_h1h[NN * C1];      // layer-1 features, fp16
__device__ float  g_out1[NN * C1];     // relu(agg + b1), fp32
__device__ __half g_h2h[NN * CLS];     // layer-2 features, fp16
__device__ float  g_als1[NN * HEADS];
__device__ float  g_ald1[NN * HEADS];
__device__ float  g_als2[NN];
__device__ float  g_ald2[NN];
__device__ int    g_cnt [NN];
__device__ int    g_rowptr[NN + 1];
__device__ int    g_csr_src[TOTE];

__device__ __forceinline__ float lrelu(float x) { return x > 0.f ? x : NEG * x; }

__device__ __forceinline__ unsigned long long pk2(float a, float b) {
    unsigned long long r;
    asm("mov.b64 %0, {%1, %2};" : "=l"(r)
        : "r"(__float_as_uint(a)), "r"(__float_as_uint(b)));
    return r;
}
__device__ __forceinline__ void fma2(unsigned long long& d,
                                     unsigned long long a, unsigned long long b) {
    asm("fma.rn.f32x2 %0, %1, %2, %0;" : "+l"(d) : "l"(a), "l"(b));
}
__device__ __forceinline__ float2 up2(unsigned long long p) {
    unsigned int lo, hi;
    asm("mov.b64 {%0, %1}, %2;" : "=r"(lo), "=r"(hi) : "l"(p));
    return make_float2(__uint_as_float(lo), __uint_as_float(hi));
}
__device__ __forceinline__ float2 h2f(unsigned int u) {
    __half2 h = *reinterpret_cast<__half2*>(&u);
    return __half22float2(h);
}
__device__ __forceinline__ unsigned int f2h(float a, float b) {
    __half2 h = __float22half2_rn(make_float2(a, b));
    return *reinterpret_cast<unsigned int*>(&h);
}
__device__ __forceinline__ float tf32r(float f) {
    unsigned r;
    asm("cvt.rna.tf32.f32 %0, %1;" : "=r"(r) : "f"(f));
    return __uint_as_float(r);
}
__device__ __forceinline__ void mma_tf32(float* c, const unsigned* a, const unsigned* b) {
    asm volatile(
        "mma.sync.aligned.m16n8k8.row.col.f32.tf32.tf32.f32 "
        "{%0,%1,%2,%3}, {%4,%5,%6,%7}, {%8,%9}, {%0,%1,%2,%3};"
        : "+f"(c[0]), "+f"(c[1]), "+f"(c[2]), "+f"(c[3])
        : "r"(a[0]), "r"(a[1]), "r"(a[2]), "r"(a[3]), "r"(b[0]), "r"(b[1]));
}

// ---------------- CSR build ----------------
__global__ void hist_kernel(const int* __restrict__ ei) {
    int q = (blockIdx.x * blockDim.x + threadIdx.x) * 4;
    if (q >= TOTE) return;
    if (q + 4 <= EE) {
        int4 d4 = *(const int4*)&ei[EE + q];
        asm volatile("red.global.add.u32 [%0], %1;" :: "l"(&g_cnt[d4.x]), "r"(1) : "memory");
        asm volatile("red.global.add.u32 [%0], %1;" :: "l"(&g_cnt[d4.y]), "r"(1) : "memory");
        asm volatile("red.global.add.u32 [%0], %1;" :: "l"(&g_cnt[d4.z]), "r"(1) : "memory");
        asm volatile("red.global.add.u32 [%0], %1;" :: "l"(&g_cnt[d4.w]), "r"(1) : "memory");
    } else {
        for (int j = 0; j < 4 && q + j < TOTE; j++) {
            int e = q + j;
            int d = (e < EE) ? ei[EE + e] : e - EE;
            asm volatile("red.global.add.u32 [%0], %1;" :: "l"(&g_cnt[d]), "r"(1) : "memory");
        }
    }
}
__global__ void scan_kernel() {
    __shared__ int sums[1024];
    const int CH = 49;
    int tid = threadIdx.x;
    int base = tid * CH;
    int s = 0;
#pragma unroll 7
    for (int j = 0; j < CH; j++) { int idx = base + j; if (idx < NN) s += g_cnt[idx]; }
    sums[tid] = s;
    __syncthreads();
    for (int off = 1; off < 1024; off <<= 1) {
        int v = (tid >= off) ? sums[tid - off] : 0;
        __syncthreads();
        sums[tid] += v;
        __syncthreads();
    }
    int run = sums[tid] - s;
    for (int j = 0; j < CH; j++) {
        int idx = base + j;
        if (idx < NN) {
            int c = g_cnt[idx];
            g_rowptr[idx] = run;
            g_cnt[idx] = run;
            run += c;
        }
    }
    if (tid == 1023) g_rowptr[NN] = sums[tid];
}
__global__ void scatter_kernel(const int* __restrict__ ei) {
    int q = (blockIdx.x * blockDim.x + threadIdx.x) * 4;
    if (q >= TOTE) return;
    if (q + 4 <= EE) {
        int4 s4 = *(const int4*)&ei[q];
        int4 d4 = *(const int4*)&ei[EE + q];
        int p0 = atomicAdd(&g_cnt[d4.x], 1);
        int p1 = atomicAdd(&g_cnt[d4.y], 1);
        int p2 = atomicAdd(&g_cnt[d4.z], 1);
        int p3 = atomicAdd(&g_cnt[d4.w], 1);
        g_csr_src[p0] = s4.x;
        g_csr_src[p1] = s4.y;
        g_csr_src[p2] = s4.z;
        g_csr_src[p3] = s4.w;
    } else {
        for (int j = 0; j < 4 && q + j < TOTE; j++) {
            int e = q + j;
            int s, d;
            if (e < EE) { s = ei[e]; d = ei[EE + e]; } else { s = d = e - EE; }
            int pos = atomicAdd(&g_cnt[d], 1);
            g_csr_src[pos] = s;
        }
    }
}

// ---------------- GEMM1 (tf32 tensor core) + fused attention logits ----------------
// block = 256 thr = 8 warps; block tile 128x128; warp tile 32(m) x 64(n)
// warps: wm = w%4 (m), wn = w/4 (n). k-tiles of 32, mma k8 sub-steps.
__global__ __launch_bounds__(256, 2) void gemm1_kernel(const float* __restrict__ x,
                                                       const float* __restrict__ W,
                                                       const float* __restrict__ att_s,
                                                       const float* __restrict__ att_d) {
    __shared__ __align__(16) float xs[128][36];    // [row][k], pad 4 -> bank-perfect frags
    __shared__ __align__(16) float ws[32][136];    // [k][col], pad 8 -> bank-perfect frags
    __shared__ __align__(16) float ps_s[128][4];
    __shared__ __align__(16) float pd_s[128][4];

    int t = threadIdx.x;
    int row0 = blockIdx.x * 128;
    int w = t >> 5, lane = t & 31;
    int wm = w & 3, wn = w >> 2;
    int q = lane >> 2, rsub = lane & 3;            // fragment coords

    if (t < 128) *(float4*)&ps_s[t][0] = make_float4(0.f, 0.f, 0.f, 0.f);
    else         *(float4*)&pd_s[t - 128][0] = make_float4(0.f, 0.f, 0.f, 0.f);

    float c[2][8][4];
#pragma unroll
    for (int mt = 0; mt < 2; mt++)
#pragma unroll
        for (int nt = 0; nt < 8; nt++)
#pragma unroll
            for (int i = 0; i < 4; i++) c[mt][nt][i] = 0.f;

    for (int k0 = 0; k0 < FIN; k0 += 32) {
        // load x tile [128 rows][32 k], cvt to tf32
#pragma unroll
        for (int j = 0; j < 4; j++) {
            int idx = t + 256 * j;                 // 1024 float4 slots
            int r = idx >> 3, kq = idx & 7;
            int gr = row0 + r;
            float4 v = make_float4(0.f, 0.f, 0.f, 0.f);
            if (gr < NN) v = *(const float4*)&x[gr * FIN + k0 + kq * 4];
            v.x = tf32r(v.x); v.y = tf32r(v.y); v.z = tf32r(v.z); v.w = tf32r(v.w);
            *(float4*)&xs[r][kq * 4] = v;
        }
        // load W tile [32 k][128 cols], cvt to tf32
#pragma unroll
        for (int j = 0; j < 4; j++) {
            int idx = t + 256 * j;
            int kk = idx >> 5, c4 = idx & 31;
            float4 v = *(const float4*)&W[(k0 + kk) * C1 + c4 * 4];
            v.x = tf32r(v.x); v.y = tf32r(v.y); v.z = tf32r(v.z); v.w = tf32r(v.w);
            *(float4*)&ws[kk][c4 * 4] = v;
        }
        __syncthreads();
#pragma unroll
        for (int ks = 0; ks < 4; ks++) {
            int kb = ks * 8;
            unsigned af[2][4];
#pragma unroll
            for (int mt = 0; mt < 2; mt++) {
                int rb = wm * 32 + mt * 16;
                af[mt][0] = __float_as_uint(xs[rb + q    ][kb + rsub    ]);
                af[mt][1] = __float_as_uint(xs[rb + q + 8][kb + rsub    ]);
                af[mt][2] = __float_as_uint(xs[rb + q    ][kb + rsub + 4]);
                af[mt][3] = __float_as_uint(xs[rb + q + 8][kb + rsub + 4]);
            }
            unsigned bf[8][2];
#pragma unroll
            for (int nt = 0; nt < 8; nt++) {
                int col = wn * 64 + nt * 8 + q;
                bf[nt][0] = __float_as_uint(ws[kb + rsub    ][col]);
                bf[nt][1] = __float_as_uint(ws[kb + rsub + 4][col]);
            }
#pragma unroll
            for (int mt = 0; mt < 2; mt++)
#pragma unroll
                for (int nt = 0; nt < 8; nt++)
                    mma_tf32(c[mt][nt], af[mt], bf[nt]);
        }
        __syncthreads();
    }

    // ---- epilogue: store h1 (fp16) + per-head logit partials ----
    // thread owns rows {wm*32+mt*16+q, +8}, cols {wn*64+nt*8+2*rsub, +1}
    float2 asv[8], adv[8];
#pragma unroll
    for (int nt = 0; nt < 8; nt++) {
        int col = wn * 64 + nt * 8 + 2 * rsub;
        asv[nt] = *(const float2*)&att_s[col];
        adv[nt] = *(const float2*)&att_d[col];
    }
#pragma unroll
    for (int mt = 0; mt < 2; mt++) {
        int rloc0 = wm * 32 + mt * 16 + q;       // local row (c0,c1)
        int rloc1 = rloc0 + 8;                   // local row (c2,c3)
        float psl0 = 0.f, psh0 = 0.f, pdl0 = 0.f, pdh0 = 0.f;
        float psl1 = 0.f, psh1 = 0.f, pdl1 = 0.f, pdh1 = 0.f;
#pragma unroll
        for (int nt = 0; nt < 8; nt++) {
            float c0 = c[mt][nt][0], c1 = c[mt][nt][1];
            float c2 = c[mt][nt][2], c3 = c[mt][nt][3];
            float s0 = c0 * asv[nt].x + c1 * asv[nt].y;
            float d0 = c0 * adv[nt].x + c1 * adv[nt].y;
            float s1 = c2 * asv[nt].x + c3 * asv[nt].y;
            float d1 = c2 * adv[nt].x + c3 * adv[nt].y;
            if (nt < 4) { psl0 += s0; pdl0 += d0; psl1 += s1; pdl1 += d1; }
            else        { psh0 += s0; pdh0 += d0; psh1 += s1; pdh1 += d1; }
            // store fp16 pairs
            int colg = wn * 64 + nt * 8 + 2 * rsub;
            int gr0 = row0 + rloc0, gr1 = row0 + rloc1;
            if (gr0 < NN) *(unsigned*)&g_h1h[gr0 * C1 + colg] = f2h(c0, c1);
            if (gr1 < NN) *(unsigned*)&g_h1h[gr1 * C1 + colg] = f2h(c2, c3);
        }
        // quad-reduce (lanes 4k..4k+3 share rows)
#pragma unroll
        for (int o = 1; o < 4; o <<= 1) {
            psl0 += __shfl_down_sync(0xffffffff, psl0, o, 4);
            psh0 += __shfl_down_sync(0xffffffff, psh0, o, 4);
            pdl0 += __shfl_down_sync(0xffffffff, pdl0, o, 4);
            pdh0 += __shfl_down_sync(0xffffffff, pdh0, o, 4);
            psl1 += __shfl_down_sync(0xffffffff, psl1, o, 4);
            psh1 += __shfl_down_sync(0xffffffff, psh1, o, 4);
            pdl1 += __shfl_down_sync(0xffffffff, pdl1, o, 4);
            pdh1 += __shfl_down_sync(0xffffffff, pdh1, o, 4);
        }
        if (rsub == 0) {
            int hlo = wn * 2, hhi = wn * 2 + 1;
            atomicAdd(&ps_s[rloc0][hlo], psl0);
            atomicAdd(&ps_s[rloc0][hhi], psh0);
            atomicAdd(&pd_s[rloc0][hlo], pdl0);
            atomicAdd(&pd_s[rloc0][hhi], pdh0);
            atomicAdd(&ps_s[rloc1][hlo], psl1);
            atomicAdd(&ps_s[rloc1][hhi], psh1);
            atomicAdd(&pd_s[rloc1][hlo], pdl1);
            atomicAdd(&pd_s[rloc1][hhi], pdh1);
        }
    }
    __syncthreads();
    if (t < 128) {
        int gr = row0 + t;
        if (gr < NN) *(float4*)&g_als1[gr * HEADS] = *(float4*)&ps_s[t][0];
    } else {
        int rr = t - 128;
        int gr = row0 + rr;
        if (gr < NN) *(float4*)&g_ald1[gr * HEADS] = *(float4*)&pd_s[rr][0];
    }
}

// ---------------- layer-1 aggregation: warp/node, fp16 gather, 4-edge batches ----------------
__global__ void agg1_kernel(const float* __restrict__ b1) {
    int gt = blockIdx.x * blockDim.x + threadIdx.x;
    int n = gt >> 5, lane = gt & 31;
    if (n >= NN) return;
    int h = lane >> 3;
    float ald = g_ald1[n * HEADS + h];
    int beg = g_rowptr[n], end = g_rowptr[n + 1];
    float4 acc = make_float4(0.f, 0.f, 0.f, 0.f);
    float den = 0.f;
    int i = beg;
    for (; i + 4 <= end; i += 4) {
        int sA = __ldg(&g_csr_src[i]);
        int sB = __ldg(&g_csr_src[i + 1]);
        int sC = __ldg(&g_csr_src[i + 2]);
        int sD = __ldg(&g_csr_src[i + 3]);
        float aA = __ldg(&g_als1[sA * HEADS + h]);
        float aB = __ldg(&g_als1[sB * HEADS + h]);
        float aC = __ldg(&g_als1[sC * HEADS + h]);
        float aD = __ldg(&g_als1[sD * HEADS + h]);
        uint2 rA = *(const uint2*)&g_h1h[sA * C1 + lane * 4];
        uint2 rB = *(const uint2*)&g_h1h[sB * C1 + lane * 4];
        uint2 rC = *(const uint2*)&g_h1h[sC * C1 + lane * 4];
        uint2 rD = *(const uint2*)&g_h1h[sD * C1 + lane * 4];
        float wA = __expf(lrelu(aA + ald));
        float wB = __expf(lrelu(aB + ald));
        float wC = __expf(lrelu(aC + ald));
        float wD = __expf(lrelu(aD + ald));
        den += (wA + wB) + (wC + wD);
        float2 A0 = h2f(rA.x), A1 = h2f(rA.y);
        float2 B0 = h2f(rB.x), B1 = h2f(rB.y);
        float2 C0 = h2f(rC.x), C1v = h2f(rC.y);
        float2 D0 = h2f(rD.x), D1 = h2f(rD.y);
        acc.x += wA * A0.x + wB * B0.x + wC * C0.x + wD * D0.x;
        acc.y += wA * A0.y + wB * B0.y + wC * C0.y + wD * D0.y;
        acc.z += wA * A1.x + wB * B1.x + wC * C1v.x + wD * D1.x;
        acc.w += wA * A1.y + wB * B1.y + wC * C1v.y + wD * D1.y;
    }
    for (; i < end; i++) {
        int s = __ldg(&g_csr_src[i]);
        float w = __expf(lrelu(__ldg(&g_als1[s * HEADS + h]) + ald));
        den += w;
        uint2 r = *(const uint2*)&g_h1h[s * C1 + lane * 4];
        float2 p0 = h2f(r.x), p1 = h2f(r.y);
        acc.x += w * p0.x; acc.y += w * p0.y;
        acc.z += w * p1.x; acc.w += w * p1.y;
    }
    float inv = 1.f / (den + 1e-16f);
    float4 bb = *(const float4*)&b1[lane * 4];
    float4 o;
    o.x = fmaxf(acc.x * inv + bb.x, 0.f);
    o.y = fmaxf(acc.y * inv + bb.y, 0.f);
    o.z = fmaxf(acc.z * inv + bb.z, 0.f);
    o.w = fmaxf(acc.w * inv + bb.w, 0.f);
    *(float4*)&g_out1[n * C1 + lane * 4] = o;
}

// ---------------- GEMM2 + layer-2 logits (h2 stored fp16) ----------------
__global__ __launch_bounds__(256) void l2gemm_kernel(const float* __restrict__ W2,
                                                     const float* __restrict__ as2,
                                                     const float* __restrict__ ad2) {
    __shared__ __align__(16) float W2s[FIN * CLS];
    __shared__ float s2s[CLS], d2s[CLS];
    int t = threadIdx.x;
    for (int i = t; i < FIN * CLS; i += 256) W2s[i] = W2[i];
    if (t < CLS) { s2s[t] = as2[t]; d2s[t] = ad2[t]; }
    __syncthreads();

    int n = blockIdx.x * blockDim.x + t;
    if (n >= NN) return;
    unsigned long long acc[20];
#pragma unroll
    for (int c = 0; c < 20; c++) acc[c] = 0ULL;

    for (int k = 0; k < FIN; k += 4) {
        float4 r4 = *(const float4*)&g_out1[n * FIN + k];
        float rv[4] = {r4.x, r4.y, r4.z, r4.w};
#pragma unroll
        for (int qq = 0; qq < 4; qq++) {
            unsigned long long rp = pk2(rv[qq], rv[qq]);
            const float* wrow = &W2s[(k + qq) * CLS];
#pragma unroll
            for (int c4 = 0; c4 < 10; c4++) {
                ulonglong2 wp = *(const ulonglong2*)&wrow[c4 * 4];
                fma2(acc[c4 * 2 + 0], rp, wp.x);
                fma2(acc[c4 * 2 + 1], rp, wp.y);
            }
        }
    }
    float ls = 0.f, ld = 0.f;
    unsigned int hp[20];
#pragma unroll
    for (int c2 = 0; c2 < 20; c2++) {
        float2 v = up2(acc[c2]);
        hp[c2] = f2h(v.x, v.y);
        ls += v.x * s2s[c2 * 2] + v.y * s2s[c2 * 2 + 1];
        ld += v.x * d2s[c2 * 2] + v.y * d2s[c2 * 2 + 1];
    }
    uint4* dst = (uint4*)&g_h2h[n * CLS];
#pragma unroll
    for (int j = 0; j < 5; j++) {
        uint4 u;
        u.x = hp[j * 4 + 0]; u.y = hp[j * 4 + 1];
        u.z = hp[j * 4 + 2]; u.w = hp[j * 4 + 3];
        dst[j] = u;
    }
    g_als2[n] = ls;
    g_ald2[n] = ld;
}

// ---------------- layer-2 aggregation + bias + log_softmax ----------------
__global__ void agg2_kernel(const float* __restrict__ b2, float* __restrict__ out) {
    int gt = blockIdx.x * blockDim.x + threadIdx.x;
    int n = gt >> 5, lane = gt & 31;
    if (n >= NN) return;
    float ald = g_ald2[n];
    int beg = g_rowptr[n], end = g_rowptr[n + 1];
    bool act = lane < 10;
    float4 acc = make_float4(0.f, 0.f, 0.f, 0.f);
    float den = 0.f;
    int i = beg;
    for (; i + 4 <= end; i += 4) {
        int sA = __ldg(&g_csr_src[i]);
        int sB = __ldg(&g_csr_src[i + 1]);
        int sC = __ldg(&g_csr_src[i + 2]);
        int sD = __ldg(&g_csr_src[i + 3]);
        float aA = __ldg(&g_als2[sA]);
        float aB = __ldg(&g_als2[sB]);
        float aC = __ldg(&g_als2[sC]);
        float aD = __ldg(&g_als2[sD]);
        uint2 rA = make_uint2(0u, 0u), rB = rA, rC = rA, rD = rA;
        if (act) {
            rA = *(const uint2*)&g_h2h[sA * CLS + lane * 4];
            rB = *(const uint2*)&g_h2h[sB * CLS + lane * 4];
            rC = *(const uint2*)&g_h2h[sC * CLS + lane * 4];
            rD = *(const uint2*)&g_h2h[sD * CLS + lane * 4];
        }
        float wA = __expf(lrelu(aA + ald));
        float wB = __expf(lrelu(aB + ald));
        float wC = __expf(lrelu(aC + ald));
        float wD = __expf(lrelu(aD + ald));
        den += (wA + wB) + (wC + wD);
        float2 A0 = h2f(rA.x), A1 = h2f(rA.y);
        float2 B0 = h2f(rB.x), B1 = h2f(rB.y);
        float2 C0 = h2f(rC.x), C1v = h2f(rC.y);
        float2 D0 = h2f(rD.x), D1 = h2f(rD.y);
        acc.x += wA * A0.x + wB * B0.x + wC * C0.x + wD * D0.x;
        acc.y += wA * A0.y + wB * B0.y + wC * C0.y + wD * D0.y;
        acc.z += wA * A1.x + wB * B1.x + wC * C1v.x + wD * D1.x;
        acc.w += wA * A1.y + wB * B1.y + wC * C1v.y + wD * D1.y;
    }
    for (; i < end; i++) {
        int s = __ldg(&g_csr_src[i]);
        float w = __expf(lrelu(__ldg(&g_als2[s]) + ald));
        den += w;
        if (act) {
            uint2 r = *(const uint2*)&g_h2h[s * CLS + lane * 4];
            float2 p0 = h2f(r.x), p1 = h2f(r.y);
            acc.x += w * p0.x; acc.y += w * p0.y;
            acc.z += w * p1.x; acc.w += w * p1.y;
        }
    }
    float inv = 1.f / (den + 1e-16f);
    float4 v = make_float4(-1e30f, -1e30f, -1e30f, -1e30f);
    if (act) {
        float4 bb = *(const float4*)&b2[lane * 4];
        v.x = acc.x * inv + bb.x;
        v.y = acc.y * inv + bb.y;
        v.z = acc.z * inv + bb.z;
        v.w = acc.w * inv + bb.w;
    }
    float m = fmaxf(fmaxf(v.x, v.y), fmaxf(v.z, v.w));
#pragma unroll
    for (int o = 16; o > 0; o >>= 1) m = fmaxf(m, __shfl_xor_sync(0xffffffff, m, o));
    float s4 = 0.f;
    if (act)
        s4 = __expf(v.x - m) + __expf(v.y - m) + __expf(v.z - m) + __expf(v.w - m);
#pragma unroll
    for (int o = 16; o > 0; o >>= 1) s4 += __shfl_xor_sync(0xffffffff, s4, o);
    float lse = m + logf(s4);
    if (act) {
        float4 r;
        r.x = v.x - lse; r.y = v.y - lse; r.z = v.z - lse; r.w = v.w - lse;
        *(float4*)&out[n * CLS + lane * 4] = r;
    }
}

// ---------------- launch ----------------
extern "C" void kernel_launch(void* const* d_in, const int* in_sizes, int n_in,
                              void* d_out, int out_size) {
    const float* x   = (const float*)d_in[0];
    const int*   ei  = (const int*)  d_in[1];
    const float* W1  = (const float*)d_in[2];
    const float* as1 = (const float*)d_in[3];
    const float* ad1 = (const float*)d_in[4];
    const float* b1  = (const float*)d_in[5];
    const float* W2  = (const float*)d_in[6];
    const float* as2 = (const float*)d_in[7];
    const float* ad2 = (const float*)d_in[8];
    const float* b2  = (const float*)d_in[9];
    float* out = (float*)d_out;

    cudaStream_t s2;
    cudaEvent_t evA, evB;
    cudaStreamCreateWithFlags(&s2, cudaStreamNonBlocking);
    cudaEventCreateWithFlags(&evA, cudaEventDisableTiming);
    cudaEventCreateWithFlags(&evB, cudaEventDisableTiming);

    cudaEventRecord(evA, 0);
    cudaStreamWaitEvent(s2, evA, 0);

    // branch A: CSR build
    void* cnt_ptr = nullptr;
    cudaGetSymbolAddress(&cnt_ptr, g_cnt);
    cudaMemsetAsync(cnt_ptr, 0, NN * sizeof(int), s2);
    hist_kernel<<<((TOTE + 3) / 4 + 255) / 256, 256, 0, s2>>>(ei);
    scan_kernel<<<1, 1024, 0, s2>>>();
    scatter_kernel<<<((TOTE + 3) / 4 + 255) / 256, 256, 0, s2>>>(ei);
    cudaEventRecord(evB, s2);

    // branch B: dense layer 1 (tensor core) + fused logits
    gemm1_kernel<<<(NN + 127) / 128, 256>>>(x, W1, as1, ad1);

    cudaStreamWaitEvent(0, evB, 0);

    agg1_kernel<<<(NN * 32 + 255) / 256, 256>>>(b1);
    l2gemm_kernel<<<(NN + 255) / 256, 256>>>(W2, as2, ad2);
    agg2_kernel<<<(NN * 32 + 255) / 256, 256>>>(b2, out);
}